// round 14
// baseline (speedup 1.0000x reference)
#include <cuda_runtime.h>
#include <cuda_fp16.h>
#include <cstdint>
#include <math.h>

// ---------------- problem constants ----------------
#define D_DIM     32
#define K_CODES   8192
#define N_ROWS    32768
#define MROWS     128                 // rows per CTA (approx kernel)
#define GRID_MAIN (N_ROWS / MROWS)    // 256
#define NTHR      256                 // 8 warps
#define SCODES    256                 // codes per stage
#define NSTAGES   (K_CODES / SCODES)  // 32
#define NCHUNK    (SCODES / 8)        // 32

// bpack tile layout: [hi 16384][lo 16384][bias 1024]
#define ST_HI     0
#define ST_LO     16384
#define ST_BIAS   32768
#define STAGE_BYTES 33792

// approx stages: hi-only, 16 KB each, TRIPLE buffered (single sync per stage)
#define ASTAGE      16384
#define SMEM_APPROX (3 * ASTAGE)      // 49152

#define MARGIN    2.0e-3f    // > 2*(9.8e-4 fp16 1-pass bound + 1.2e-7 bias jitter)
#define LOSS_SCALE 67108864.0         // 2^26 fixed-point for deterministic loss sum

// ---------------- device globals (no cudaMalloc allowed) ----------------
__device__ __align__(1024) uint32_t g_ah2[N_ROWS * 16];        // z hi fp16x2 A-frag
__device__ __align__(1024) uint32_t g_al2[N_ROWS * 16];        // z lo fp16x2 A-frag
__device__ __align__(1024) char     g_bpack[NSTAGES * STAGE_BYTES];
__device__ __align__(16)   float    g_codes_norm[K_CODES * D_DIM];
__device__ __align__(16)   float    g_znorm[N_ROWS * D_DIM];
__device__ int   g_cnt;
__device__ int   g_list[N_ROWS];
__device__ int   g_flag[N_ROWS];          // 0 = clean, else list position + 1
__device__ float g_cand_s[N_ROWS * 4];
__device__ int   g_cand_i[N_ROWS * 4];
__device__ unsigned long long g_loss_acc; // fixed-point loss accumulator
__device__ unsigned int      g_done;      // completed vq_out blocks

// ---------------- helpers ----------------
static __device__ __forceinline__ uint32_t smem_u32(const void* p) {
    uint32_t a;
    asm("{ .reg .u64 t; cvta.to.shared.u64 t, %1; cvt.u32.u64 %0, t; }" : "=r"(a) : "l"(p));
    return a;
}
#define CP_ASYNC16(dst, src) \
    asm volatile("cp.async.cg.shared.global [%0], [%1], 16;" :: "r"(dst), "l"(src) : "memory")
#define CP_COMMIT() asm volatile("cp.async.commit_group;" ::: "memory")
#define CP_WAIT(n)  asm volatile("cp.async.wait_group %0;" :: "n"(n) : "memory")

static __device__ __forceinline__ void mma_f16(float& c0, float& c1, float& c2, float& c3,
                                               uint32_t a0, uint32_t a1, uint32_t a2, uint32_t a3,
                                               uint32_t b0, uint32_t b1) {
    asm volatile("mma.sync.aligned.m16n8k16.row.col.f32.f16.f16.f32 "
                 "{%0,%1,%2,%3}, {%4,%5,%6,%7}, {%8,%9}, {%0,%1,%2,%3};"
                 : "+f"(c0), "+f"(c1), "+f"(c2), "+f"(c3)
                 : "r"(a0), "r"(a1), "r"(a2), "r"(a3), "r"(b0), "r"(b1));
}
static __device__ __forceinline__ uint32_t pack_h2(float x, float y) {
    __half2 h = __floats2half2_rn(x, y);
    return *reinterpret_cast<uint32_t*>(&h);
}

// ---------------- prep: codes only (z prep fused into vq_approx) ----------------
__global__ void vq_prep_codes(const float* __restrict__ emb) {
    const int gid  = blockIdx.x * 256 + threadIdx.x;    // 16384 threads
    const int t    = gid >> 1;
    const int half = gid & 1;
    if (gid == 0) { g_cnt = 0; g_loss_acc = 0ull; g_done = 0u; }

    const float4* ep = reinterpret_cast<const float4*>(emb + (size_t)t * D_DIM) + half * 4;
    float v[16]; float ps = 0.0f;
#pragma unroll
    for (int i = 0; i < 4; ++i) {
        float4 q = ep[i];
        v[4*i+0]=q.x; v[4*i+1]=q.y; v[4*i+2]=q.z; v[4*i+3]=q.w;
        ps += q.x*q.x + q.y*q.y + q.z*q.z + q.w*q.w;
    }
    const float ss = ps + __shfl_xor_sync(0xffffffffu, ps, 1);
    const float inv = 1.0f / fmaxf(sqrtf(ss), 1e-12f);

    float x[16], hi[16], lo[16];
    float ps2 = 0.0f;
    float* cn = g_codes_norm + (size_t)t * D_DIM + half * 16;
#pragma unroll
    for (int c = 0; c < 16; ++c) {
        x[c] = v[c] * inv;
        cn[c] = x[c];
        ps2 += x[c] * x[c];
        float h = __half2float(__float2half_rn(x[c]));
        hi[c] = h;
        lo[c] = x[c] - h;
    }
    const float ss2 = ps2 + __shfl_xor_sync(0xffffffffu, ps2, 1);

    const int tile = t >> 8, ci = t & 255;
    char* base = g_bpack + (size_t)tile * STAGE_BYTES;
    uint32_t* bh = reinterpret_cast<uint32_t*>(base + ST_HI + ci * 64);
    uint32_t* bl = reinterpret_cast<uint32_t*>(base + ST_LO + ci * 64);
    // slot layout: for tg in 0..3, half h writes slots 4*tg+2*h+{0,1} from local k2 = tg, tg+4
#pragma unroll
    for (int tg = 0; tg < 4; ++tg) {
        const int s0 = 4 * tg + 2 * half;
        bh[s0]     = pack_h2(hi[2*tg],     hi[2*tg+1]);
        bh[s0 + 1] = pack_h2(hi[2*(tg+4)], hi[2*(tg+4)+1]);
        bl[s0]     = pack_h2(lo[2*tg],     lo[2*tg+1]);
        bl[s0 + 1] = pack_h2(lo[2*(tg+4)], lo[2*(tg+4)+1]);
    }
    if (half == 0)
        reinterpret_cast<float*>(base + ST_BIAS)[ci] = -0.5f * ss2;
}

// octal top-2 update: values (p0,p1)=codes n0,n0+1; (p2,p3)=+8,+9; (p4,p5)=+16,+17; (p6,p7)=+24,+25
static __device__ __forceinline__ void upd8(float p0, float p1, float p2, float p3,
                                            float p4, float p5, float p6, float p7,
                                            int n0, float& best, float& sec, int& bi) {
    float ma = fmaxf(p0, p1), mb = fmaxf(p2, p3);
    float mc = fmaxf(p4, p5), md = fmaxf(p6, p7);
    float MA = fmaxf(ma, mb), MB = fmaxf(mc, md);
    float M  = fmaxf(MA, MB);
    if (__builtin_expect(M > best, 0)) {
        float secq, Mo; int idx;
        if (MA >= MB) {
            Mo = MB;
            if (ma >= mb) { secq = fmaxf(fminf(p0, p1), mb); idx = (p1 > p0) ? n0 + 1  : n0;      }
            else          { secq = fmaxf(fminf(p2, p3), ma); idx = (p3 > p2) ? n0 + 9  : n0 + 8;  }
        } else {
            Mo = MA;
            if (mc >= md) { secq = fmaxf(fminf(p4, p5), md); idx = (p5 > p4) ? n0 + 17 : n0 + 16; }
            else          { secq = fmaxf(fminf(p6, p7), mc); idx = (p7 > p6) ? n0 + 25 : n0 + 24; }
        }
        sec  = fmaxf(best, fmaxf(secq, Mo));
        best = M;
        bi   = idx;
    } else {
        sec = fmaxf(sec, M);
    }
}

// ---------------- approx: fused z-prep + 1-pass fp16 GEMM, 32-code iters, top-2 margin ----------------
// Triple-buffered stages: ONE __syncthreads per stage (copy(t+2) targets the buffer whose
// last readers finished compute(t-1) strictly before this iteration's barrier).
__global__ void __launch_bounds__(NTHR, 4)
vq_approx(const float* __restrict__ z, float* __restrict__ idx_out) {
    extern __shared__ __align__(16) char smem[];
    const uint32_t sb = smem_u32(smem);
    const int tid = threadIdx.x;
    const int w   = tid >> 5;
    const int g   = (tid & 31) >> 2;
    const int tg  = tid & 3;
    const int rb  = blockIdx.x;
    const int r0  = rb * MROWS + w * 16 + g;
    const int r1  = r0 + 8;

    // ---- fused z prep: 2 threads per row; stage hi A-words in smem overlay (buffer 0) ----
    {
        uint32_t* ah_s = reinterpret_cast<uint32_t*>(smem);   // 128 rows x 16 words = 8 KB
        const int rl   = tid >> 1;
        const int half = tid & 1;
        const int row  = rb * MROWS + rl;

        const float4* zp = reinterpret_cast<const float4*>(z + (size_t)row * D_DIM) + half * 4;
        float v[16]; float ps = 0.0f;
#pragma unroll
        for (int i = 0; i < 4; ++i) {
            float4 q = zp[i];
            v[4*i+0]=q.x; v[4*i+1]=q.y; v[4*i+2]=q.z; v[4*i+3]=q.w;
            ps += q.x*q.x + q.y*q.y + q.z*q.z + q.w*q.w;
        }
        const float ss = ps + __shfl_xor_sync(0xffffffffu, ps, 1);
        const float inv = 1.0f / fmaxf(sqrtf(ss), 1e-12f);

        float hi[16], lo[16];
        float* zn = g_znorm + (size_t)row * D_DIM + half * 16;
#pragma unroll
        for (int c = 0; c < 16; ++c) {
            float x = v[c] * inv;
            zn[c] = x;
            float h = __half2float(__float2half_rn(x));
            hi[c] = h;
            lo[c] = x - h;
        }
        uint32_t* ah = g_ah2 + (size_t)row * 16 + half * 8;
        uint32_t* al = g_al2 + (size_t)row * 16 + half * 8;
#pragma unroll
        for (int k2 = 0; k2 < 8; ++k2) {
            uint32_t ph = pack_h2(hi[2*k2], hi[2*k2+1]);
            ah[k2] = ph;                                   // global (for vq_fix)
            al[k2] = pack_h2(lo[2*k2], lo[2*k2+1]);
            ah_s[rl * 16 + half * 8 + k2] = ph;            // smem staging (for frags)
        }
    }
    __syncthreads();

    uint32_t ahi[2][4];
    {
        const uint32_t* S0 = reinterpret_cast<const uint32_t*>(smem) + (w * 16 + g) * 16;
        const uint32_t* S1 = S0 + 8 * 16;
#pragma unroll
        for (int ks = 0; ks < 2; ++ks) {
            ahi[ks][0] = S0[ks*8 + tg];     ahi[ks][1] = S1[ks*8 + tg];
            ahi[ks][2] = S0[ks*8 + tg + 4]; ahi[ks][3] = S1[ks*8 + tg + 4];
        }
    }
    __syncthreads();   // staging reads done before copy(0) overwrites the overlay

    auto stage_copy = [&](int t) {
        const char* src = g_bpack + (size_t)t * STAGE_BYTES + ST_HI;
        const uint32_t dst = sb + (uint32_t)(t % 3) * ASTAGE;
#pragma unroll
        for (int j = 0; j < 4; ++j) {
            int u = tid + j * NTHR;               // 0..1023 -> 16 KB
            CP_ASYNC16(dst + u * 16, src + (size_t)u * 16);
        }
        CP_COMMIT();
    };

    float best0 = -1e30f, sec0 = -1e30f, best1 = -1e30f, sec1 = -1e30f;
    int   bi0 = 0, bi1 = 0;

    stage_copy(0);
    stage_copy(1);
    for (int t = 0; t < NSTAGES; ++t) {
        if (t + 1 < NSTAGES) CP_WAIT(1);          // copy(t) complete; copy(t+1) may fly
        else                 CP_WAIT(0);
        __syncthreads();                          // single barrier per stage
        if (t + 2 < NSTAGES) stage_copy(t + 2);   // targets buf (t-1)%3 — readers are past it

        const char* st = smem + (t % 3) * ASTAGE;
        const int base = t * SCODES;

        for (int ch = 0; ch < NCHUNK; ch += 4) {
            uint4 Ha = *reinterpret_cast<const uint4*>(st + ((ch    ) * 8 + g) * 64 + tg * 16);
            uint4 Hb = *reinterpret_cast<const uint4*>(st + ((ch + 1) * 8 + g) * 64 + tg * 16);
            uint4 Hc = *reinterpret_cast<const uint4*>(st + ((ch + 2) * 8 + g) * 64 + tg * 16);
            uint4 Hd = *reinterpret_cast<const uint4*>(st + ((ch + 3) * 8 + g) * 64 + tg * 16);
            float a0 = 0.f, a1 = 0.f, a2 = 0.f, a3 = 0.f;
            float b0 = 0.f, b1 = 0.f, b2 = 0.f, b3 = 0.f;
            float c0 = 0.f, c1 = 0.f, c2 = 0.f, c3 = 0.f;
            float d0 = 0.f, d1 = 0.f, d2 = 0.f, d3 = 0.f;
            mma_f16(a0,a1,a2,a3, ahi[0][0],ahi[0][1],ahi[0][2],ahi[0][3], Ha.x, Ha.y);
            mma_f16(a0,a1,a2,a3, ahi[1][0],ahi[1][1],ahi[1][2],ahi[1][3], Ha.z, Ha.w);
            mma_f16(b0,b1,b2,b3, ahi[0][0],ahi[0][1],ahi[0][2],ahi[0][3], Hb.x, Hb.y);
            mma_f16(b0,b1,b2,b3, ahi[1][0],ahi[1][1],ahi[1][2],ahi[1][3], Hb.z, Hb.w);
            mma_f16(c0,c1,c2,c3, ahi[0][0],ahi[0][1],ahi[0][2],ahi[0][3], Hc.x, Hc.y);
            mma_f16(c0,c1,c2,c3, ahi[1][0],ahi[1][1],ahi[1][2],ahi[1][3], Hc.z, Hc.w);
            mma_f16(d0,d1,d2,d3, ahi[0][0],ahi[0][1],ahi[0][2],ahi[0][3], Hd.x, Hd.y);
            mma_f16(d0,d1,d2,d3, ahi[1][0],ahi[1][1],ahi[1][2],ahi[1][3], Hd.z, Hd.w);

            const int n0 = base + ch * 8 + 2 * tg;
            upd8(a0,a1, b0,b1, c0,c1, d0,d1, n0, best0, sec0, bi0);   // row r0
            upd8(a2,a3, b2,b3, c2,c3, d2,d3, n0, best1, sec1, bi1);   // row r1
        }
    }

    // merge (best, sec, idx) across the 4 tg lanes
#pragma unroll
    for (int off = 1; off < 4; off <<= 1) {
        float ob0 = __shfl_xor_sync(0xffffffffu, best0, off);
        float os0 = __shfl_xor_sync(0xffffffffu, sec0,  off);
        int   oi0 = __shfl_xor_sync(0xffffffffu, bi0,   off);
        float ob1 = __shfl_xor_sync(0xffffffffu, best1, off);
        float os1 = __shfl_xor_sync(0xffffffffu, sec1,  off);
        int   oi1 = __shfl_xor_sync(0xffffffffu, bi1,   off);
        float ns0 = fmaxf(fminf(best0, ob0), fmaxf(sec0, os0));
        float ns1 = fmaxf(fminf(best1, ob1), fmaxf(sec1, os1));
        bi0 = (ob0 > best0) ? oi0 : bi0;  best0 = fmaxf(best0, ob0);  sec0 = ns0;
        bi1 = (ob1 > best1) ? oi1 : bi1;  best1 = fmaxf(best1, ob1);  sec1 = ns1;
    }

    if (tg == 0) {
        idx_out[r0] = (float)bi0;
        idx_out[r1] = (float)bi1;
        int f0 = 0, f1 = 0;
        if (best0 - sec0 <= MARGIN) { int p = atomicAdd(&g_cnt, 1); g_list[p] = r0; f0 = p + 1; }
        if (best1 - sec1 <= MARGIN) { int p = atomicAdd(&g_cnt, 1); g_list[p] = r1; f1 = p + 1; }
        g_flag[r0] = f0;               // unconditional store -> no reset pass needed
        g_flag[r1] = f1;
    }
}

// ---------------- fix: exact R4 3-pass, split by code-quarter ----------------
__global__ void __launch_bounds__(NTHR, 2)
vq_fix() {
    const int cnt = g_cnt;
    if (cnt == 0) return;
    const int nbatch = (cnt + 15) >> 4;
    const int nwork  = nbatch * 4;

    __shared__ int   rows_s[16];
    __shared__ float cs[8][16];
    __shared__ int   cidx[8][16];
    const int tid = threadIdx.x;
    const int w   = tid >> 5;
    const int g   = (tid & 31) >> 2;
    const int tg  = tid & 3;

    for (int i0 = blockIdx.x; i0 < nwork; i0 += gridDim.x) {
        const int batch = i0 >> 2, q = i0 & 3;
        const int nrows = min(16, cnt - batch * 16);
        if (tid < 16) rows_s[tid] = g_list[batch * 16 + min(tid, nrows - 1)];
        __syncthreads();

        const int r0 = rows_s[g], r1 = rows_s[g + 8];
        uint32_t ahi[2][4], alo[2][4];
        {
            const uint32_t* A0 = g_ah2 + (size_t)r0 * 16;
            const uint32_t* A1 = g_ah2 + (size_t)r1 * 16;
            const uint32_t* L0 = g_al2 + (size_t)r0 * 16;
            const uint32_t* L1 = g_al2 + (size_t)r1 * 16;
#pragma unroll
            for (int ks = 0; ks < 2; ++ks) {
                ahi[ks][0] = A0[ks*8 + tg];     ahi[ks][1] = A1[ks*8 + tg];
                ahi[ks][2] = A0[ks*8 + tg + 4]; ahi[ks][3] = A1[ks*8 + tg + 4];
                alo[ks][0] = L0[ks*8 + tg];     alo[ks][1] = L1[ks*8 + tg];
                alo[ks][2] = L0[ks*8 + tg + 4]; alo[ks][3] = L1[ks*8 + tg + 4];
            }
        }

        float best0 = -1e30f, best1 = -1e30f;
        int   bi0 = 0, bi1 = 0;

#pragma unroll 4
        for (int ch = 0; ch < 32; ++ch) {                 // 256 codes per warp
            const int c8 = q * 2048 + w * 256 + ch * 8;
            const int stage = c8 >> 8, ci = c8 & 255;
            const char* st = g_bpack + (size_t)stage * STAGE_BYTES;
            uint4 H = *reinterpret_cast<const uint4*>(st + ST_HI + (ci + g) * 64 + tg * 16);
            uint4 L = *reinterpret_cast<const uint4*>(st + ST_LO + (ci + g) * 64 + tg * 16);
            float2 bb = *reinterpret_cast<const float2*>(st + ST_BIAS + (ci + 2 * tg) * 4);

            float c0 = bb.x, c1 = bb.y, c2 = bb.x, c3 = bb.y;
            // exact R4 accumulation order
            mma_f16(c0,c1,c2,c3, ahi[0][0],ahi[0][1],ahi[0][2],ahi[0][3], H.x, H.y);
            mma_f16(c0,c1,c2,c3, ahi[1][0],ahi[1][1],ahi[1][2],ahi[1][3], H.z, H.w);
            mma_f16(c0,c1,c2,c3, ahi[0][0],ahi[0][1],ahi[0][2],ahi[0][3], L.x, L.y);
            mma_f16(c0,c1,c2,c3, ahi[1][0],ahi[1][1],ahi[1][2],ahi[1][3], L.z, L.w);
            mma_f16(c0,c1,c2,c3, alo[0][0],alo[0][1],alo[0][2],alo[0][3], H.x, H.y);
            mma_f16(c0,c1,c2,c3, alo[1][0],alo[1][1],alo[1][2],alo[1][3], H.z, H.w);

            const int n0 = c8 + 2 * tg;
            if (c0 > best0) { best0 = c0; bi0 = n0;     }
            if (c1 > best0) { best0 = c1; bi0 = n0 + 1; }
            if (c2 > best1) { best1 = c2; bi1 = n0;     }
            if (c3 > best1) { best1 = c3; bi1 = n0 + 1; }
        }

#pragma unroll
        for (int off = 1; off < 4; off <<= 1) {
            float ob0 = __shfl_xor_sync(0xffffffffu, best0, off);
            int   oi0 = __shfl_xor_sync(0xffffffffu, bi0,   off);
            float ob1 = __shfl_xor_sync(0xffffffffu, best1, off);
            int   oi1 = __shfl_xor_sync(0xffffffffu, bi1,   off);
            if (ob0 > best0 || (ob0 == best0 && oi0 < bi0)) { best0 = ob0; bi0 = oi0; }
            if (ob1 > best1 || (ob1 == best1 && oi1 < bi1)) { best1 = ob1; bi1 = oi1; }
        }
        if (tg == 0) {
            cs[w][g]     = best0;  cidx[w][g]     = bi0;
            cs[w][g + 8] = best1;  cidx[w][g + 8] = bi1;
        }
        __syncthreads();

        if (tid < 16) {
            float b = -1e30f; int bi = 0;
#pragma unroll
            for (int w2 = 0; w2 < 8; ++w2) {
                float s = cs[w2][tid]; int ii = cidx[w2][tid];
                if (s > b || (s == b && ii < bi)) { b = s; bi = ii; }
            }
            const int p = batch * 16 + tid;
            g_cand_s[p * 4 + q] = b;
            g_cand_i[p * 4 + q] = bi;
        }
        __syncthreads();
    }
}

// ---------------- out: merge flagged rows + z_q gather + deterministic loss ----------------
// 4 threads per row (quarter-row each); grid 512 x 256.
__global__ void vq_out(float* __restrict__ zq_out, float* __restrict__ idx_out,
                       float* __restrict__ loss_out) {
    __shared__ float red[256];
    const int gid = blockIdx.x * 256 + threadIdx.x;    // 131072 threads
    const int row = gid >> 2;
    const int qt  = gid & 3;

    int b;
    const int f = g_flag[row];
    if (f == 0) {
        b = (int)idx_out[row];
    } else {
        const int t = f - 1;
        float bs = -1e30f; b = 0;
#pragma unroll
        for (int q = 0; q < 4; ++q) {
            float s = g_cand_s[t * 4 + q];
            int   i = g_cand_i[t * 4 + q];
            if (s > bs) { bs = s; b = i; }    // strict > keeps lowest-idx quarter on ties
        }
        if (qt == 0) idx_out[row] = (float)b;
    }

    const float4* e4 = reinterpret_cast<const float4*>(g_codes_norm + (size_t)b * D_DIM) + qt * 2;
    const float4* z4 = reinterpret_cast<const float4*>(g_znorm + (size_t)row * D_DIM) + qt * 2;
    float4* oq = reinterpret_cast<float4*>(zq_out + (size_t)row * D_DIM) + qt * 2;
    float lsum = 0.0f;
#pragma unroll
    for (int i = 0; i < 2; ++i) {
        float4 q = e4[i];
        float4 zn = z4[i];
        float d0 = q.x - zn.x, d1 = q.y - zn.y, d2 = q.z - zn.z, d3 = q.w - zn.w;
        lsum += d0*d0 + d1*d1 + d2*d2 + d3*d3;
        oq[i] = q;
    }
    red[threadIdx.x] = lsum;
    __syncthreads();
#pragma unroll
    for (int s = 128; s > 0; s >>= 1) {
        if (threadIdx.x < s) red[threadIdx.x] += red[threadIdx.x + s];
        __syncthreads();
    }
    if (threadIdx.x == 0) {
        long long q = __double2ll_rn((double)red[0] * LOSS_SCALE);
        atomicAdd(&g_loss_acc, (unsigned long long)q);
        __threadfence();
        unsigned int done = atomicAdd(&g_done, 1u);
        if (done == gridDim.x - 1) {
            double total = (double)(long long)g_loss_acc / LOSS_SCALE;
            loss_out[0] = (float)(1.25 * total / (double)(N_ROWS * D_DIM));
        }
    }
}

// ---------------- launch ----------------
extern "C" void kernel_launch(void* const* d_in, const int* in_sizes, int n_in,
                              void* d_out, int out_size) {
    const float* z   = (const float*)d_in[0];   // [32,1024,32]
    const float* emb = (const float*)d_in[1];   // [8192,32]
    float* out = (float*)d_out;

    float* zq_out   = out;                               // 1048576 floats
    float* loss_out = out + (size_t)N_ROWS * D_DIM;      // 1 float
    float* idx_out  = loss_out + 1;                      // 32768 floats

    cudaFuncSetAttribute(vq_approx, cudaFuncAttributeMaxDynamicSharedMemorySize, SMEM_APPROX);

    vq_prep_codes<<<64, 256>>>(emb);
    vq_approx<<<GRID_MAIN, NTHR, SMEM_APPROX>>>(z, idx_out);
    vq_fix<<<1024, NTHR>>>();
    vq_out<<<512, 256>>>(zq_out, idx_out, loss_out);
}

// round 15
// speedup vs baseline: 1.0195x; 1.0195x over previous
#include <cuda_runtime.h>
#include <cuda_fp16.h>
#include <cstdint>
#include <math.h>

// ---------------- problem constants ----------------
#define D_DIM     32
#define K_CODES   8192
#define N_ROWS    32768
#define MROWS     128                 // rows per CTA (approx kernel)
#define GRID_MAIN (N_ROWS / MROWS)    // 256
#define NTHR      256                 // 8 warps
#define SCODES    256                 // codes per stage
#define NSTAGES   (K_CODES / SCODES)  // 32
#define NCHUNK    (SCODES / 8)        // 32

// bpack tile layout: [hi 16384][lo 16384][bias 1024]
#define ST_HI     0
#define ST_LO     16384
#define ST_BIAS   32768
#define STAGE_BYTES 33792

// approx stages: hi-only, 16 KB each, double buffered (R13 proven form)
#define ASTAGE      16384
#define SMEM_APPROX (2 * ASTAGE)      // 32768

#define MARGIN    2.0e-3f    // > 2*(9.8e-4 fp16 1-pass bound + 1.2e-7 bias jitter)
#define LOSS_SCALE 67108864.0         // 2^26 fixed-point for deterministic loss sum

// ---------------- device globals (no cudaMalloc allowed) ----------------
__device__ __align__(1024) uint32_t g_ah2[N_ROWS * 16];        // z hi fp16x2 A-frag
__device__ __align__(1024) uint32_t g_al2[N_ROWS * 16];        // z lo fp16x2 A-frag
__device__ __align__(1024) char     g_bpack[NSTAGES * STAGE_BYTES];
__device__ __align__(16)   float    g_codes_norm[K_CODES * D_DIM];
__device__ __align__(16)   float    g_znorm[N_ROWS * D_DIM];
__device__ int   g_cnt;
__device__ int   g_list[N_ROWS];
__device__ int   g_flag[N_ROWS];          // 0 = clean, else list position + 1
__device__ float g_cand_s[N_ROWS * 4];
__device__ int   g_cand_i[N_ROWS * 4];
__device__ unsigned long long g_loss_acc; // fixed-point loss accumulator
__device__ unsigned int      g_done;      // completed vq_out blocks

// ---------------- helpers ----------------
static __device__ __forceinline__ uint32_t smem_u32(const void* p) {
    uint32_t a;
    asm("{ .reg .u64 t; cvta.to.shared.u64 t, %1; cvt.u32.u64 %0, t; }" : "=r"(a) : "l"(p));
    return a;
}
#define CP_ASYNC16(dst, src) \
    asm volatile("cp.async.cg.shared.global [%0], [%1], 16;" :: "r"(dst), "l"(src) : "memory")
#define CP_COMMIT() asm volatile("cp.async.commit_group;" ::: "memory")
#define CP_WAIT(n)  asm volatile("cp.async.wait_group %0;" :: "n"(n) : "memory")

static __device__ __forceinline__ void mma_f16(float& c0, float& c1, float& c2, float& c3,
                                               uint32_t a0, uint32_t a1, uint32_t a2, uint32_t a3,
                                               uint32_t b0, uint32_t b1) {
    asm volatile("mma.sync.aligned.m16n8k16.row.col.f32.f16.f16.f32 "
                 "{%0,%1,%2,%3}, {%4,%5,%6,%7}, {%8,%9}, {%0,%1,%2,%3};"
                 : "+f"(c0), "+f"(c1), "+f"(c2), "+f"(c3)
                 : "r"(a0), "r"(a1), "r"(a2), "r"(a3), "r"(b0), "r"(b1));
}
static __device__ __forceinline__ uint32_t pack_h2(float x, float y) {
    __half2 h = __floats2half2_rn(x, y);
    return *reinterpret_cast<uint32_t*>(&h);
}

// ---------------- prep: codes only (z prep fused into vq_approx) ----------------
__global__ void vq_prep_codes(const float* __restrict__ emb) {
    const int gid  = blockIdx.x * 256 + threadIdx.x;    // 16384 threads
    const int t    = gid >> 1;
    const int half = gid & 1;
    if (gid == 0) { g_cnt = 0; g_loss_acc = 0ull; g_done = 0u; }

    const float4* ep = reinterpret_cast<const float4*>(emb + (size_t)t * D_DIM) + half * 4;
    float v[16]; float ps = 0.0f;
#pragma unroll
    for (int i = 0; i < 4; ++i) {
        float4 q = ep[i];
        v[4*i+0]=q.x; v[4*i+1]=q.y; v[4*i+2]=q.z; v[4*i+3]=q.w;
        ps += q.x*q.x + q.y*q.y + q.z*q.z + q.w*q.w;
    }
    const float ss = ps + __shfl_xor_sync(0xffffffffu, ps, 1);
    const float inv = 1.0f / fmaxf(sqrtf(ss), 1e-12f);

    float x[16], hi[16], lo[16];
    float ps2 = 0.0f;
    float* cn = g_codes_norm + (size_t)t * D_DIM + half * 16;
#pragma unroll
    for (int c = 0; c < 16; ++c) {
        x[c] = v[c] * inv;
        cn[c] = x[c];
        ps2 += x[c] * x[c];
        float h = __half2float(__float2half_rn(x[c]));
        hi[c] = h;
        lo[c] = x[c] - h;
    }
    const float ss2 = ps2 + __shfl_xor_sync(0xffffffffu, ps2, 1);

    const int tile = t >> 8, ci = t & 255;
    char* base = g_bpack + (size_t)tile * STAGE_BYTES;
    uint32_t* bh = reinterpret_cast<uint32_t*>(base + ST_HI + ci * 64);
    uint32_t* bl = reinterpret_cast<uint32_t*>(base + ST_LO + ci * 64);
    // slot layout: for tg in 0..3, half h writes slots 4*tg+2*h+{0,1} from local k2 = tg, tg+4
#pragma unroll
    for (int tg = 0; tg < 4; ++tg) {
        const int s0 = 4 * tg + 2 * half;
        bh[s0]     = pack_h2(hi[2*tg],     hi[2*tg+1]);
        bh[s0 + 1] = pack_h2(hi[2*(tg+4)], hi[2*(tg+4)+1]);
        bl[s0]     = pack_h2(lo[2*tg],     lo[2*tg+1]);
        bl[s0 + 1] = pack_h2(lo[2*(tg+4)], lo[2*(tg+4)+1]);
    }
    if (half == 0)
        reinterpret_cast<float*>(base + ST_BIAS)[ci] = -0.5f * ss2;
}

// octal top-2 update: values (p0,p1)=codes n0,n0+1; (p2,p3)=+8,+9; (p4,p5)=+16,+17; (p6,p7)=+24,+25
static __device__ __forceinline__ void upd8(float p0, float p1, float p2, float p3,
                                            float p4, float p5, float p6, float p7,
                                            int n0, float& best, float& sec, int& bi) {
    float ma = fmaxf(p0, p1), mb = fmaxf(p2, p3);
    float mc = fmaxf(p4, p5), md = fmaxf(p6, p7);
    float MA = fmaxf(ma, mb), MB = fmaxf(mc, md);
    float M  = fmaxf(MA, MB);
    if (__builtin_expect(M > best, 0)) {
        float secq, Mo; int idx;
        if (MA >= MB) {
            Mo = MB;
            if (ma >= mb) { secq = fmaxf(fminf(p0, p1), mb); idx = (p1 > p0) ? n0 + 1  : n0;      }
            else          { secq = fmaxf(fminf(p2, p3), ma); idx = (p3 > p2) ? n0 + 9  : n0 + 8;  }
        } else {
            Mo = MA;
            if (mc >= md) { secq = fmaxf(fminf(p4, p5), md); idx = (p5 > p4) ? n0 + 17 : n0 + 16; }
            else          { secq = fmaxf(fminf(p6, p7), mc); idx = (p7 > p6) ? n0 + 25 : n0 + 24; }
        }
        sec  = fmaxf(best, fmaxf(secq, Mo));
        best = M;
        bi   = idx;
    } else {
        sec = fmaxf(sec, M);
    }
}

// ---------------- approx: fused z-prep + 1-pass fp16 GEMM, 32-code iters, top-2 margin ----------------
__global__ void __launch_bounds__(NTHR, 4)
vq_approx(const float* __restrict__ z, float* __restrict__ idx_out) {
    extern __shared__ __align__(16) char smem[];
    const uint32_t sb = smem_u32(smem);
    const int tid = threadIdx.x;
    const int w   = tid >> 5;
    const int g   = (tid & 31) >> 2;
    const int tg  = tid & 3;
    const int rb  = blockIdx.x;
    const int r0  = rb * MROWS + w * 16 + g;
    const int r1  = r0 + 8;

    // ---- fused z prep: 2 threads per row; stage hi A-words in smem overlay ----
    {
        uint32_t* ah_s = reinterpret_cast<uint32_t*>(smem);   // 128 rows x 16 words = 8 KB (overlay)
        const int rl   = tid >> 1;
        const int half = tid & 1;
        const int row  = rb * MROWS + rl;

        const float4* zp = reinterpret_cast<const float4*>(z + (size_t)row * D_DIM) + half * 4;
        float v[16]; float ps = 0.0f;
#pragma unroll
        for (int i = 0; i < 4; ++i) {
            float4 q = zp[i];
            v[4*i+0]=q.x; v[4*i+1]=q.y; v[4*i+2]=q.z; v[4*i+3]=q.w;
            ps += q.x*q.x + q.y*q.y + q.z*q.z + q.w*q.w;
        }
        const float ss = ps + __shfl_xor_sync(0xffffffffu, ps, 1);
        const float inv = 1.0f / fmaxf(sqrtf(ss), 1e-12f);

        float hi[16], lo[16];
        float* zn = g_znorm + (size_t)row * D_DIM + half * 16;
#pragma unroll
        for (int c = 0; c < 16; ++c) {
            float x = v[c] * inv;
            zn[c] = x;
            float h = __half2float(__float2half_rn(x));
            hi[c] = h;
            lo[c] = x - h;
        }
        uint32_t* ah = g_ah2 + (size_t)row * 16 + half * 8;
        uint32_t* al = g_al2 + (size_t)row * 16 + half * 8;
#pragma unroll
        for (int k2 = 0; k2 < 8; ++k2) {
            uint32_t ph = pack_h2(hi[2*k2], hi[2*k2+1]);
            ah[k2] = ph;                                   // global (for vq_fix)
            al[k2] = pack_h2(lo[2*k2], lo[2*k2+1]);
            ah_s[rl * 16 + half * 8 + k2] = ph;            // smem staging (for frags)
        }
    }
    __syncthreads();

    uint32_t ahi[2][4];
    {
        const uint32_t* S0 = reinterpret_cast<const uint32_t*>(smem) + (w * 16 + g) * 16;
        const uint32_t* S1 = S0 + 8 * 16;
#pragma unroll
        for (int ks = 0; ks < 2; ++ks) {
            ahi[ks][0] = S0[ks*8 + tg];     ahi[ks][1] = S1[ks*8 + tg];
            ahi[ks][2] = S0[ks*8 + tg + 4]; ahi[ks][3] = S1[ks*8 + tg + 4];
        }
    }
    __syncthreads();   // staging reads done before stage_copy(0) overwrites the overlay

    auto stage_copy = [&](int t) {
        const char* src = g_bpack + (size_t)t * STAGE_BYTES + ST_HI;
        const uint32_t dst = sb + (t & 1) * ASTAGE;
#pragma unroll
        for (int j = 0; j < 4; ++j) {
            int u = tid + j * NTHR;               // 0..1023 -> 16 KB
            CP_ASYNC16(dst + u * 16, src + (size_t)u * 16);
        }
        CP_COMMIT();
    };

    float best0 = -1e30f, sec0 = -1e30f, best1 = -1e30f, sec1 = -1e30f;
    int   bi0 = 0, bi1 = 0;

    stage_copy(0);
    for (int t = 0; t < NSTAGES; ++t) {
        if (t + 1 < NSTAGES) { stage_copy(t + 1); CP_WAIT(1); }
        else                 { CP_WAIT(0); }
        __syncthreads();

        const char* st = smem + (t & 1) * ASTAGE;
        const int base = t * SCODES;

        for (int ch = 0; ch < NCHUNK; ch += 4) {
            uint4 Ha = *reinterpret_cast<const uint4*>(st + ((ch    ) * 8 + g) * 64 + tg * 16);
            uint4 Hb = *reinterpret_cast<const uint4*>(st + ((ch + 1) * 8 + g) * 64 + tg * 16);
            uint4 Hc = *reinterpret_cast<const uint4*>(st + ((ch + 2) * 8 + g) * 64 + tg * 16);
            uint4 Hd = *reinterpret_cast<const uint4*>(st + ((ch + 3) * 8 + g) * 64 + tg * 16);
            float a0 = 0.f, a1 = 0.f, a2 = 0.f, a3 = 0.f;
            float b0 = 0.f, b1 = 0.f, b2 = 0.f, b3 = 0.f;
            float c0 = 0.f, c1 = 0.f, c2 = 0.f, c3 = 0.f;
            float d0 = 0.f, d1 = 0.f, d2 = 0.f, d3 = 0.f;
            mma_f16(a0,a1,a2,a3, ahi[0][0],ahi[0][1],ahi[0][2],ahi[0][3], Ha.x, Ha.y);
            mma_f16(a0,a1,a2,a3, ahi[1][0],ahi[1][1],ahi[1][2],ahi[1][3], Ha.z, Ha.w);
            mma_f16(b0,b1,b2,b3, ahi[0][0],ahi[0][1],ahi[0][2],ahi[0][3], Hb.x, Hb.y);
            mma_f16(b0,b1,b2,b3, ahi[1][0],ahi[1][1],ahi[1][2],ahi[1][3], Hb.z, Hb.w);
            mma_f16(c0,c1,c2,c3, ahi[0][0],ahi[0][1],ahi[0][2],ahi[0][3], Hc.x, Hc.y);
            mma_f16(c0,c1,c2,c3, ahi[1][0],ahi[1][1],ahi[1][2],ahi[1][3], Hc.z, Hc.w);
            mma_f16(d0,d1,d2,d3, ahi[0][0],ahi[0][1],ahi[0][2],ahi[0][3], Hd.x, Hd.y);
            mma_f16(d0,d1,d2,d3, ahi[1][0],ahi[1][1],ahi[1][2],ahi[1][3], Hd.z, Hd.w);

            const int n0 = base + ch * 8 + 2 * tg;
            upd8(a0,a1, b0,b1, c0,c1, d0,d1, n0, best0, sec0, bi0);   // row r0
            upd8(a2,a3, b2,b3, c2,c3, d2,d3, n0, best1, sec1, bi1);   // row r1
        }
        __syncthreads();
    }

    // merge (best, sec, idx) across the 4 tg lanes
#pragma unroll
    for (int off = 1; off < 4; off <<= 1) {
        float ob0 = __shfl_xor_sync(0xffffffffu, best0, off);
        float os0 = __shfl_xor_sync(0xffffffffu, sec0,  off);
        int   oi0 = __shfl_xor_sync(0xffffffffu, bi0,   off);
        float ob1 = __shfl_xor_sync(0xffffffffu, best1, off);
        float os1 = __shfl_xor_sync(0xffffffffu, sec1,  off);
        int   oi1 = __shfl_xor_sync(0xffffffffu, bi1,   off);
        float ns0 = fmaxf(fminf(best0, ob0), fmaxf(sec0, os0));
        float ns1 = fmaxf(fminf(best1, ob1), fmaxf(sec1, os1));
        bi0 = (ob0 > best0) ? oi0 : bi0;  best0 = fmaxf(best0, ob0);  sec0 = ns0;
        bi1 = (ob1 > best1) ? oi1 : bi1;  best1 = fmaxf(best1, ob1);  sec1 = ns1;
    }

    if (tg == 0) {
        idx_out[r0] = (float)bi0;
        idx_out[r1] = (float)bi1;
        int f0 = 0, f1 = 0;
        if (best0 - sec0 <= MARGIN) { int p = atomicAdd(&g_cnt, 1); g_list[p] = r0; f0 = p + 1; }
        if (best1 - sec1 <= MARGIN) { int p = atomicAdd(&g_cnt, 1); g_list[p] = r1; f1 = p + 1; }
        g_flag[r0] = f0;               // unconditional store -> no reset pass needed
        g_flag[r1] = f1;
    }
}

// ---------------- fix: exact R4 3-pass, split by code-quarter ----------------
__global__ void __launch_bounds__(NTHR, 2)
vq_fix() {
    const int cnt = g_cnt;
    if (cnt == 0) return;
    const int nbatch = (cnt + 15) >> 4;
    const int nwork  = nbatch * 4;

    __shared__ int   rows_s[16];
    __shared__ float cs[8][16];
    __shared__ int   cidx[8][16];
    const int tid = threadIdx.x;
    const int w   = tid >> 5;
    const int g   = (tid & 31) >> 2;
    const int tg  = tid & 3;

    for (int i0 = blockIdx.x; i0 < nwork; i0 += gridDim.x) {
        const int batch = i0 >> 2, q = i0 & 3;
        const int nrows = min(16, cnt - batch * 16);
        if (tid < 16) rows_s[tid] = g_list[batch * 16 + min(tid, nrows - 1)];
        __syncthreads();

        const int r0 = rows_s[g], r1 = rows_s[g + 8];
        uint32_t ahi[2][4], alo[2][4];
        {
            const uint32_t* A0 = g_ah2 + (size_t)r0 * 16;
            const uint32_t* A1 = g_ah2 + (size_t)r1 * 16;
            const uint32_t* L0 = g_al2 + (size_t)r0 * 16;
            const uint32_t* L1 = g_al2 + (size_t)r1 * 16;
#pragma unroll
            for (int ks = 0; ks < 2; ++ks) {
                ahi[ks][0] = A0[ks*8 + tg];     ahi[ks][1] = A1[ks*8 + tg];
                ahi[ks][2] = A0[ks*8 + tg + 4]; ahi[ks][3] = A1[ks*8 + tg + 4];
                alo[ks][0] = L0[ks*8 + tg];     alo[ks][1] = L1[ks*8 + tg];
                alo[ks][2] = L0[ks*8 + tg + 4]; alo[ks][3] = L1[ks*8 + tg + 4];
            }
        }

        float best0 = -1e30f, best1 = -1e30f;
        int   bi0 = 0, bi1 = 0;

#pragma unroll 4
        for (int ch = 0; ch < 32; ++ch) {                 // 256 codes per warp
            const int c8 = q * 2048 + w * 256 + ch * 8;
            const int stage = c8 >> 8, ci = c8 & 255;
            const char* st = g_bpack + (size_t)stage * STAGE_BYTES;
            uint4 H = *reinterpret_cast<const uint4*>(st + ST_HI + (ci + g) * 64 + tg * 16);
            uint4 L = *reinterpret_cast<const uint4*>(st + ST_LO + (ci + g) * 64 + tg * 16);
            float2 bb = *reinterpret_cast<const float2*>(st + ST_BIAS + (ci + 2 * tg) * 4);

            float c0 = bb.x, c1 = bb.y, c2 = bb.x, c3 = bb.y;
            // exact R4 accumulation order
            mma_f16(c0,c1,c2,c3, ahi[0][0],ahi[0][1],ahi[0][2],ahi[0][3], H.x, H.y);
            mma_f16(c0,c1,c2,c3, ahi[1][0],ahi[1][1],ahi[1][2],ahi[1][3], H.z, H.w);
            mma_f16(c0,c1,c2,c3, ahi[0][0],ahi[0][1],ahi[0][2],ahi[0][3], L.x, L.y);
            mma_f16(c0,c1,c2,c3, ahi[1][0],ahi[1][1],ahi[1][2],ahi[1][3], L.z, L.w);
            mma_f16(c0,c1,c2,c3, alo[0][0],alo[0][1],alo[0][2],alo[0][3], H.x, H.y);
            mma_f16(c0,c1,c2,c3, alo[1][0],alo[1][1],alo[1][2],alo[1][3], H.z, H.w);

            const int n0 = c8 + 2 * tg;
            if (c0 > best0) { best0 = c0; bi0 = n0;     }
            if (c1 > best0) { best0 = c1; bi0 = n0 + 1; }
            if (c2 > best1) { best1 = c2; bi1 = n0;     }
            if (c3 > best1) { best1 = c3; bi1 = n0 + 1; }
        }

#pragma unroll
        for (int off = 1; off < 4; off <<= 1) {
            float ob0 = __shfl_xor_sync(0xffffffffu, best0, off);
            int   oi0 = __shfl_xor_sync(0xffffffffu, bi0,   off);
            float ob1 = __shfl_xor_sync(0xffffffffu, best1, off);
            int   oi1 = __shfl_xor_sync(0xffffffffu, bi1,   off);
            if (ob0 > best0 || (ob0 == best0 && oi0 < bi0)) { best0 = ob0; bi0 = oi0; }
            if (ob1 > best1 || (ob1 == best1 && oi1 < bi1)) { best1 = ob1; bi1 = oi1; }
        }
        if (tg == 0) {
            cs[w][g]     = best0;  cidx[w][g]     = bi0;
            cs[w][g + 8] = best1;  cidx[w][g + 8] = bi1;
        }
        __syncthreads();

        if (tid < 16) {
            float b = -1e30f; int bi = 0;
#pragma unroll
            for (int w2 = 0; w2 < 8; ++w2) {
                float s = cs[w2][tid]; int ii = cidx[w2][tid];
                if (s > b || (s == b && ii < bi)) { b = s; bi = ii; }
            }
            const int p = batch * 16 + tid;
            g_cand_s[p * 4 + q] = b;
            g_cand_i[p * 4 + q] = bi;
        }
        __syncthreads();
    }
}

// ---------------- out: merge flagged rows + z_q gather + deterministic loss ----------------
// 8 threads per row (one float4 each); grid 1024 x 256.
__global__ void vq_out(float* __restrict__ zq_out, float* __restrict__ idx_out,
                       float* __restrict__ loss_out) {
    __shared__ float red[256];
    const int gid = blockIdx.x * 256 + threadIdx.x;    // 262144 threads
    const int row = gid >> 3;
    const int oct = gid & 7;

    int b;
    const int f = g_flag[row];
    if (f == 0) {
        b = (int)idx_out[row];
    } else {
        const int t = f - 1;
        float bs = -1e30f; b = 0;
#pragma unroll
        for (int q = 0; q < 4; ++q) {
            float s = g_cand_s[t * 4 + q];
            int   i = g_cand_i[t * 4 + q];
            if (s > bs) { bs = s; b = i; }    // strict > keeps lowest-idx quarter on ties
        }
        if (oct == 0) idx_out[row] = (float)b;
    }

    const float4* e4 = reinterpret_cast<const float4*>(g_codes_norm + (size_t)b * D_DIM) + oct;
    const float4* z4 = reinterpret_cast<const float4*>(g_znorm + (size_t)row * D_DIM) + oct;
    float4* oq = reinterpret_cast<float4*>(zq_out + (size_t)row * D_DIM) + oct;

    float4 q = *e4;
    float4 zn = *z4;
    float d0 = q.x - zn.x, d1 = q.y - zn.y, d2 = q.z - zn.z, d3 = q.w - zn.w;
    float lsum = d0*d0 + d1*d1 + d2*d2 + d3*d3;
    *oq = q;

    red[threadIdx.x] = lsum;
    __syncthreads();
#pragma unroll
    for (int s = 128; s > 0; s >>= 1) {
        if (threadIdx.x < s) red[threadIdx.x] += red[threadIdx.x + s];
        __syncthreads();
    }
    if (threadIdx.x == 0) {
        long long qq = __double2ll_rn((double)red[0] * LOSS_SCALE);
        atomicAdd(&g_loss_acc, (unsigned long long)qq);
        __threadfence();
        unsigned int done = atomicAdd(&g_done, 1u);
        if (done == gridDim.x - 1) {
            double total = (double)(long long)g_loss_acc / LOSS_SCALE;
            loss_out[0] = (float)(1.25 * total / (double)(N_ROWS * D_DIM));
        }
    }
}

// ---------------- launch ----------------
extern "C" void kernel_launch(void* const* d_in, const int* in_sizes, int n_in,
                              void* d_out, int out_size) {
    const float* z   = (const float*)d_in[0];   // [32,1024,32]
    const float* emb = (const float*)d_in[1];   // [8192,32]
    float* out = (float*)d_out;

    float* zq_out   = out;                               // 1048576 floats
    float* loss_out = out + (size_t)N_ROWS * D_DIM;      // 1 float
    float* idx_out  = loss_out + 1;                      // 32768 floats

    cudaFuncSetAttribute(vq_approx, cudaFuncAttributeMaxDynamicSharedMemorySize, SMEM_APPROX);

    vq_prep_codes<<<64, 256>>>(emb);
    vq_approx<<<GRID_MAIN, NTHR, SMEM_APPROX>>>(z, idx_out);
    vq_fix<<<1024, NTHR>>>();
    vq_out<<<1024, 256>>>(zq_out, idx_out, loss_out);
}

// round 16
// speedup vs baseline: 1.0798x; 1.0591x over previous
#include <cuda_runtime.h>
#include <cuda_fp16.h>
#include <cstdint>
#include <math.h>

// ---------------- problem constants ----------------
#define D_DIM     32
#define K_CODES   8192
#define N_ROWS    32768
#define MROWS     128                 // rows per CTA (approx kernel)
#define NQUART    4                   // code quarters
#define GRID_APPROX ((N_ROWS / MROWS) * NQUART)   // 1024
#define NTHR      256                 // 8 warps
#define SCODES    256                 // codes per stage
#define QSTAGES   8                   // stages per quarter (2048 codes)
#define NCHUNK    (SCODES / 8)        // 32

// bpack tile layout: [hi 16384][lo 16384][bias 1024]
#define ST_HI     0
#define ST_LO     16384
#define ST_BIAS   32768
#define STAGE_BYTES 33792

// approx stages: hi-only, 16 KB each, double buffered
#define ASTAGE      16384
#define SMEM_APPROX (2 * ASTAGE)      // 32768

#define MARGIN    2.0e-3f    // > 2*(9.8e-4 fp16 1-pass bound + 1.2e-7 bias jitter)
#define LOSS_SCALE 67108864.0         // 2^26 fixed-point for deterministic loss sum

// ---------------- device globals (no cudaMalloc allowed) ----------------
__device__ __align__(1024) uint32_t g_ah2[N_ROWS * 16];        // z hi fp16x2 A-frag
__device__ __align__(1024) uint32_t g_al2[N_ROWS * 16];        // z lo fp16x2 A-frag
__device__ __align__(1024) char     g_bpack[(K_CODES / SCODES) * STAGE_BYTES];
__device__ __align__(16)   float    g_codes_norm[K_CODES * D_DIM];
__device__ __align__(16)   float    g_znorm[N_ROWS * D_DIM];
__device__ int   g_cnt;
__device__ int   g_list[N_ROWS];
__device__ int   g_flag[N_ROWS];          // 0 = clean, else list position + 1
__device__ float g_cand_s[N_ROWS * 4];    // fix quarter candidates
__device__ int   g_cand_i[N_ROWS * 4];
__device__ float g_q_s[N_ROWS * NQUART];  // approx quarter best
__device__ float g_q_sec[N_ROWS * NQUART];// approx quarter second (conservative)
__device__ int   g_q_i[N_ROWS * NQUART];  // approx quarter best idx
__device__ unsigned long long g_loss_acc; // fixed-point loss accumulator
__device__ unsigned int      g_done;      // completed vq_out blocks

// ---------------- helpers ----------------
static __device__ __forceinline__ uint32_t smem_u32(const void* p) {
    uint32_t a;
    asm("{ .reg .u64 t; cvta.to.shared.u64 t, %1; cvt.u32.u64 %0, t; }" : "=r"(a) : "l"(p));
    return a;
}
#define CP_ASYNC16(dst, src) \
    asm volatile("cp.async.cg.shared.global [%0], [%1], 16;" :: "r"(dst), "l"(src) : "memory")
#define CP_COMMIT() asm volatile("cp.async.commit_group;" ::: "memory")
#define CP_WAIT(n)  asm volatile("cp.async.wait_group %0;" :: "n"(n) : "memory")

static __device__ __forceinline__ void mma_f16(float& c0, float& c1, float& c2, float& c3,
                                               uint32_t a0, uint32_t a1, uint32_t a2, uint32_t a3,
                                               uint32_t b0, uint32_t b1) {
    asm volatile("mma.sync.aligned.m16n8k16.row.col.f32.f16.f16.f32 "
                 "{%0,%1,%2,%3}, {%4,%5,%6,%7}, {%8,%9}, {%0,%1,%2,%3};"
                 : "+f"(c0), "+f"(c1), "+f"(c2), "+f"(c3)
                 : "r"(a0), "r"(a1), "r"(a2), "r"(a3), "r"(b0), "r"(b1));
}
static __device__ __forceinline__ uint32_t pack_h2(float x, float y) {
    __half2 h = __floats2half2_rn(x, y);
    return *reinterpret_cast<uint32_t*>(&h);
}

// ---------------- prep: z rows (blocks 0..255) + codes (blocks 256..319) ----------------
__global__ void vq_prep(const float* __restrict__ z, const float* __restrict__ emb) {
    const int bx  = blockIdx.x;
    const int tid = threadIdx.x;

    if (bx < 256) {
        const int gid  = bx * 256 + tid;        // 65536 threads
        const int row  = gid >> 1;
        const int half = gid & 1;
        if (gid == 0) { g_cnt = 0; g_loss_acc = 0ull; g_done = 0u; }

        const float4* zp = reinterpret_cast<const float4*>(z + (size_t)row * D_DIM) + half * 4;
        float v[16]; float ps = 0.0f;
#pragma unroll
        for (int i = 0; i < 4; ++i) {
            float4 q = zp[i];
            v[4*i+0]=q.x; v[4*i+1]=q.y; v[4*i+2]=q.z; v[4*i+3]=q.w;
            ps += q.x*q.x + q.y*q.y + q.z*q.z + q.w*q.w;
        }
        const float ss = ps + __shfl_xor_sync(0xffffffffu, ps, 1);
        const float inv = 1.0f / fmaxf(sqrtf(ss), 1e-12f);

        float hi[16], lo[16];
        float* zn = g_znorm + (size_t)row * D_DIM + half * 16;
#pragma unroll
        for (int c = 0; c < 16; ++c) {
            float x = v[c] * inv;
            zn[c] = x;
            float h = __half2float(__float2half_rn(x));
            hi[c] = h;
            lo[c] = x - h;
        }
        uint32_t* ah = g_ah2 + (size_t)row * 16 + half * 8;
        uint32_t* al = g_al2 + (size_t)row * 16 + half * 8;
#pragma unroll
        for (int k2 = 0; k2 < 8; ++k2) {
            ah[k2] = pack_h2(hi[2*k2], hi[2*k2+1]);
            al[k2] = pack_h2(lo[2*k2], lo[2*k2+1]);
        }
    } else {
        const int gid  = (bx - 256) * 256 + tid;    // 16384 threads
        const int t    = gid >> 1;
        const int half = gid & 1;

        const float4* ep = reinterpret_cast<const float4*>(emb + (size_t)t * D_DIM) + half * 4;
        float v[16]; float ps = 0.0f;
#pragma unroll
        for (int i = 0; i < 4; ++i) {
            float4 q = ep[i];
            v[4*i+0]=q.x; v[4*i+1]=q.y; v[4*i+2]=q.z; v[4*i+3]=q.w;
            ps += q.x*q.x + q.y*q.y + q.z*q.z + q.w*q.w;
        }
        const float ss = ps + __shfl_xor_sync(0xffffffffu, ps, 1);
        const float inv = 1.0f / fmaxf(sqrtf(ss), 1e-12f);

        float x[16], hi[16], lo[16];
        float ps2 = 0.0f;
        float* cn = g_codes_norm + (size_t)t * D_DIM + half * 16;
#pragma unroll
        for (int c = 0; c < 16; ++c) {
            x[c] = v[c] * inv;
            cn[c] = x[c];
            ps2 += x[c] * x[c];
            float h = __half2float(__float2half_rn(x[c]));
            hi[c] = h;
            lo[c] = x[c] - h;
        }
        const float ss2 = ps2 + __shfl_xor_sync(0xffffffffu, ps2, 1);

        const int tile = t >> 8, ci = t & 255;
        char* base = g_bpack + (size_t)tile * STAGE_BYTES;
        uint32_t* bh = reinterpret_cast<uint32_t*>(base + ST_HI + ci * 64);
        uint32_t* bl = reinterpret_cast<uint32_t*>(base + ST_LO + ci * 64);
#pragma unroll
        for (int tg = 0; tg < 4; ++tg) {
            const int s0 = 4 * tg + 2 * half;
            bh[s0]     = pack_h2(hi[2*tg],     hi[2*tg+1]);
            bh[s0 + 1] = pack_h2(hi[2*(tg+4)], hi[2*(tg+4)+1]);
            bl[s0]     = pack_h2(lo[2*tg],     lo[2*tg+1]);
            bl[s0 + 1] = pack_h2(lo[2*(tg+4)], lo[2*(tg+4)+1]);
        }
        if (half == 0)
            reinterpret_cast<float*>(base + ST_BIAS)[ci] = -0.5f * ss2;
    }
}

// octal top-2 update (R13-proven)
static __device__ __forceinline__ void upd8(float p0, float p1, float p2, float p3,
                                            float p4, float p5, float p6, float p7,
                                            int n0, float& best, float& sec, int& bi) {
    float ma = fmaxf(p0, p1), mb = fmaxf(p2, p3);
    float mc = fmaxf(p4, p5), md = fmaxf(p6, p7);
    float MA = fmaxf(ma, mb), MB = fmaxf(mc, md);
    float M  = fmaxf(MA, MB);
    if (__builtin_expect(M > best, 0)) {
        float secq, Mo; int idx;
        if (MA >= MB) {
            Mo = MB;
            if (ma >= mb) { secq = fmaxf(fminf(p0, p1), mb); idx = (p1 > p0) ? n0 + 1  : n0;      }
            else          { secq = fmaxf(fminf(p2, p3), ma); idx = (p3 > p2) ? n0 + 9  : n0 + 8;  }
        } else {
            Mo = MA;
            if (mc >= md) { secq = fmaxf(fminf(p4, p5), md); idx = (p5 > p4) ? n0 + 17 : n0 + 16; }
            else          { secq = fmaxf(fminf(p6, p7), mc); idx = (p7 > p6) ? n0 + 25 : n0 + 24; }
        }
        sec  = fmaxf(best, fmaxf(secq, Mo));
        best = M;
        bi   = idx;
    } else {
        sec = fmaxf(sec, M);
    }
}

// ---------------- approx: quartered 1-pass fp16 GEMM (128 rows x 2048 codes per CTA) ----------------
__global__ void __launch_bounds__(NTHR, 4)
vq_approx(float* __restrict__ idx_unused) {
    extern __shared__ __align__(16) char smem[];
    const uint32_t sb = smem_u32(smem);
    const int tid = threadIdx.x;
    const int w   = tid >> 5;
    const int g   = (tid & 31) >> 2;
    const int tg  = tid & 3;
    const int rb  = blockIdx.x >> 2;          // row block 0..255
    const int qq  = blockIdx.x & 3;           // code quarter 0..3
    const int r0  = rb * MROWS + w * 16 + g;
    const int r1  = r0 + 8;

    uint32_t ahi[2][4];
    {
        const uint32_t* A0 = g_ah2 + (size_t)r0 * 16;
        const uint32_t* A1 = g_ah2 + (size_t)r1 * 16;
#pragma unroll
        for (int ks = 0; ks < 2; ++ks) {
            ahi[ks][0] = A0[ks*8 + tg];     ahi[ks][1] = A1[ks*8 + tg];
            ahi[ks][2] = A0[ks*8 + tg + 4]; ahi[ks][3] = A1[ks*8 + tg + 4];
        }
    }

    auto stage_copy = [&](int s) {            // s = 0..7 local stage
        const char* src = g_bpack + (size_t)(qq * QSTAGES + s) * STAGE_BYTES + ST_HI;
        const uint32_t dst = sb + (s & 1) * ASTAGE;
#pragma unroll
        for (int j = 0; j < 4; ++j) {
            int u = tid + j * NTHR;           // 0..1023 -> 16 KB
            CP_ASYNC16(dst + u * 16, src + (size_t)u * 16);
        }
        CP_COMMIT();
    };

    float best0 = -1e30f, sec0 = -1e30f, best1 = -1e30f, sec1 = -1e30f;
    int   bi0 = qq * 2048, bi1 = qq * 2048;

    stage_copy(0);
    for (int t = 0; t < QSTAGES; ++t) {
        if (t + 1 < QSTAGES) { stage_copy(t + 1); CP_WAIT(1); }
        else                 { CP_WAIT(0); }
        __syncthreads();

        const char* st = smem + (t & 1) * ASTAGE;
        const int base = (qq * QSTAGES + t) * SCODES;

        for (int ch = 0; ch < NCHUNK; ch += 4) {
            uint4 Ha = *reinterpret_cast<const uint4*>(st + ((ch    ) * 8 + g) * 64 + tg * 16);
            uint4 Hb = *reinterpret_cast<const uint4*>(st + ((ch + 1) * 8 + g) * 64 + tg * 16);
            uint4 Hc = *reinterpret_cast<const uint4*>(st + ((ch + 2) * 8 + g) * 64 + tg * 16);
            uint4 Hd = *reinterpret_cast<const uint4*>(st + ((ch + 3) * 8 + g) * 64 + tg * 16);
            float a0 = 0.f, a1 = 0.f, a2 = 0.f, a3 = 0.f;
            float b0 = 0.f, b1 = 0.f, b2 = 0.f, b3 = 0.f;
            float c0 = 0.f, c1 = 0.f, c2 = 0.f, c3 = 0.f;
            float d0 = 0.f, d1 = 0.f, d2 = 0.f, d3 = 0.f;
            mma_f16(a0,a1,a2,a3, ahi[0][0],ahi[0][1],ahi[0][2],ahi[0][3], Ha.x, Ha.y);
            mma_f16(a0,a1,a2,a3, ahi[1][0],ahi[1][1],ahi[1][2],ahi[1][3], Ha.z, Ha.w);
            mma_f16(b0,b1,b2,b3, ahi[0][0],ahi[0][1],ahi[0][2],ahi[0][3], Hb.x, Hb.y);
            mma_f16(b0,b1,b2,b3, ahi[1][0],ahi[1][1],ahi[1][2],ahi[1][3], Hb.z, Hb.w);
            mma_f16(c0,c1,c2,c3, ahi[0][0],ahi[0][1],ahi[0][2],ahi[0][3], Hc.x, Hc.y);
            mma_f16(c0,c1,c2,c3, ahi[1][0],ahi[1][1],ahi[1][2],ahi[1][3], Hc.z, Hc.w);
            mma_f16(d0,d1,d2,d3, ahi[0][0],ahi[0][1],ahi[0][2],ahi[0][3], Hd.x, Hd.y);
            mma_f16(d0,d1,d2,d3, ahi[1][0],ahi[1][1],ahi[1][2],ahi[1][3], Hd.z, Hd.w);

            const int n0 = base + ch * 8 + 2 * tg;
            upd8(a0,a1, b0,b1, c0,c1, d0,d1, n0, best0, sec0, bi0);   // row r0
            upd8(a2,a3, b2,b3, c2,c3, d2,d3, n0, best1, sec1, bi1);   // row r1
        }
        __syncthreads();
    }

    // merge (best, sec, idx) across the 4 tg lanes
#pragma unroll
    for (int off = 1; off < 4; off <<= 1) {
        float ob0 = __shfl_xor_sync(0xffffffffu, best0, off);
        float os0 = __shfl_xor_sync(0xffffffffu, sec0,  off);
        int   oi0 = __shfl_xor_sync(0xffffffffu, bi0,   off);
        float ob1 = __shfl_xor_sync(0xffffffffu, best1, off);
        float os1 = __shfl_xor_sync(0xffffffffu, sec1,  off);
        int   oi1 = __shfl_xor_sync(0xffffffffu, bi1,   off);
        float ns0 = fmaxf(fminf(best0, ob0), fmaxf(sec0, os0));
        float ns1 = fmaxf(fminf(best1, ob1), fmaxf(sec1, os1));
        bi0 = (ob0 > best0) ? oi0 : bi0;  best0 = fmaxf(best0, ob0);  sec0 = ns0;
        bi1 = (ob1 > best1) ? oi1 : bi1;  best1 = fmaxf(best1, ob1);  sec1 = ns1;
    }

    if (tg == 0) {
        g_q_s[r0 * NQUART + qq]   = best0;
        g_q_sec[r0 * NQUART + qq] = sec0;
        g_q_i[r0 * NQUART + qq]   = bi0;
        g_q_s[r1 * NQUART + qq]   = best1;
        g_q_sec[r1 * NQUART + qq] = sec1;
        g_q_i[r1 * NQUART + qq]   = bi1;
    }
}

// ---------------- merge quarters + flag rows (1 thread / row) ----------------
__global__ void vq_merge_flag(float* __restrict__ idx_out) {
    const int row = blockIdx.x * 256 + threadIdx.x;    // grid 128
    float best = -1e30f; int bi = 0, wq = 0;
#pragma unroll
    for (int q = 0; q < 4; ++q) {                      // ascending q == ascending idx range
        float b = g_q_s[row * NQUART + q];
        if (b > best) { best = b; bi = g_q_i[row * NQUART + q]; wq = q; }
    }
    float sec = -1e30f;
#pragma unroll
    for (int q = 0; q < 4; ++q) {
        float v = (q == wq) ? g_q_sec[row * NQUART + q] : g_q_s[row * NQUART + q];
        sec = fmaxf(sec, v);
    }
    idx_out[row] = (float)bi;
    int f = 0;
    if (best - sec <= MARGIN) { int p = atomicAdd(&g_cnt, 1); g_list[p] = row; f = p + 1; }
    g_flag[row] = f;
}

// ---------------- fix: exact R4 3-pass, split by code-quarter ----------------
__global__ void __launch_bounds__(NTHR, 2)
vq_fix() {
    const int cnt = g_cnt;
    if (cnt == 0) return;
    const int nbatch = (cnt + 15) >> 4;
    const int nwork  = nbatch * 4;

    __shared__ int   rows_s[16];
    __shared__ float cs[8][16];
    __shared__ int   cidx[8][16];
    const int tid = threadIdx.x;
    const int w   = tid >> 5;
    const int g   = (tid & 31) >> 2;
    const int tg  = tid & 3;

    for (int i0 = blockIdx.x; i0 < nwork; i0 += gridDim.x) {
        const int batch = i0 >> 2, q = i0 & 3;
        const int nrows = min(16, cnt - batch * 16);
        if (tid < 16) rows_s[tid] = g_list[batch * 16 + min(tid, nrows - 1)];
        __syncthreads();

        const int r0 = rows_s[g], r1 = rows_s[g + 8];
        uint32_t ahi[2][4], alo[2][4];
        {
            const uint32_t* A0 = g_ah2 + (size_t)r0 * 16;
            const uint32_t* A1 = g_ah2 + (size_t)r1 * 16;
            const uint32_t* L0 = g_al2 + (size_t)r0 * 16;
            const uint32_t* L1 = g_al2 + (size_t)r1 * 16;
#pragma unroll
            for (int ks = 0; ks < 2; ++ks) {
                ahi[ks][0] = A0[ks*8 + tg];     ahi[ks][1] = A1[ks*8 + tg];
                ahi[ks][2] = A0[ks*8 + tg + 4]; ahi[ks][3] = A1[ks*8 + tg + 4];
                alo[ks][0] = L0[ks*8 + tg];     alo[ks][1] = L1[ks*8 + tg];
                alo[ks][2] = L0[ks*8 + tg + 4]; alo[ks][3] = L1[ks*8 + tg + 4];
            }
        }

        float best0 = -1e30f, best1 = -1e30f;
        int   bi0 = 0, bi1 = 0;

#pragma unroll 4
        for (int ch = 0; ch < 32; ++ch) {                 // 256 codes per warp
            const int c8 = q * 2048 + w * 256 + ch * 8;
            const int stage = c8 >> 8, ci = c8 & 255;
            const char* st = g_bpack + (size_t)stage * STAGE_BYTES;
            uint4 H = *reinterpret_cast<const uint4*>(st + ST_HI + (ci + g) * 64 + tg * 16);
            uint4 L = *reinterpret_cast<const uint4*>(st + ST_LO + (ci + g) * 64 + tg * 16);
            float2 bb = *reinterpret_cast<const float2*>(st + ST_BIAS + (ci + 2 * tg) * 4);

            float c0 = bb.x, c1 = bb.y, c2 = bb.x, c3 = bb.y;
            // exact R4 accumulation order
            mma_f16(c0,c1,c2,c3, ahi[0][0],ahi[0][1],ahi[0][2],ahi[0][3], H.x, H.y);
            mma_f16(c0,c1,c2,c3, ahi[1][0],ahi[1][1],ahi[1][2],ahi[1][3], H.z, H.w);
            mma_f16(c0,c1,c2,c3, ahi[0][0],ahi[0][1],ahi[0][2],ahi[0][3], L.x, L.y);
            mma_f16(c0,c1,c2,c3, ahi[1][0],ahi[1][1],ahi[1][2],ahi[1][3], L.z, L.w);
            mma_f16(c0,c1,c2,c3, alo[0][0],alo[0][1],alo[0][2],alo[0][3], H.x, H.y);
            mma_f16(c0,c1,c2,c3, alo[1][0],alo[1][1],alo[1][2],alo[1][3], H.z, H.w);

            const int n0 = c8 + 2 * tg;
            if (c0 > best0) { best0 = c0; bi0 = n0;     }
            if (c1 > best0) { best0 = c1; bi0 = n0 + 1; }
            if (c2 > best1) { best1 = c2; bi1 = n0;     }
            if (c3 > best1) { best1 = c3; bi1 = n0 + 1; }
        }

#pragma unroll
        for (int off = 1; off < 4; off <<= 1) {
            float ob0 = __shfl_xor_sync(0xffffffffu, best0, off);
            int   oi0 = __shfl_xor_sync(0xffffffffu, bi0,   off);
            float ob1 = __shfl_xor_sync(0xffffffffu, best1, off);
            int   oi1 = __shfl_xor_sync(0xffffffffu, bi1,   off);
            if (ob0 > best0 || (ob0 == best0 && oi0 < bi0)) { best0 = ob0; bi0 = oi0; }
            if (ob1 > best1 || (ob1 == best1 && oi1 < bi1)) { best1 = ob1; bi1 = oi1; }
        }
        if (tg == 0) {
            cs[w][g]     = best0;  cidx[w][g]     = bi0;
            cs[w][g + 8] = best1;  cidx[w][g + 8] = bi1;
        }
        __syncthreads();

        if (tid < 16) {
            float b = -1e30f; int bi = 0;
#pragma unroll
            for (int w2 = 0; w2 < 8; ++w2) {
                float s = cs[w2][tid]; int ii = cidx[w2][tid];
                if (s > b || (s == b && ii < bi)) { b = s; bi = ii; }
            }
            const int p = batch * 16 + tid;
            g_cand_s[p * 4 + q] = b;
            g_cand_i[p * 4 + q] = bi;
        }
        __syncthreads();
    }
}

// ---------------- out: merge flagged rows + z_q gather + deterministic loss ----------------
// 8 threads per row (one float4 each); grid 1024 x 256.
__global__ void vq_out(float* __restrict__ zq_out, float* __restrict__ idx_out,
                       float* __restrict__ loss_out) {
    __shared__ float red[256];
    const int gid = blockIdx.x * 256 + threadIdx.x;    // 262144 threads
    const int row = gid >> 3;
    const int oct = gid & 7;

    int b;
    const int f = g_flag[row];
    if (f == 0) {
        b = (int)idx_out[row];
    } else {
        const int t = f - 1;
        float bs = -1e30f; b = 0;
#pragma unroll
        for (int q = 0; q < 4; ++q) {
            float s = g_cand_s[t * 4 + q];
            int   i = g_cand_i[t * 4 + q];
            if (s > bs) { bs = s; b = i; }    // strict > keeps lowest-idx quarter on ties
        }
        if (oct == 0) idx_out[row] = (float)b;
    }

    const float4* e4 = reinterpret_cast<const float4*>(g_codes_norm + (size_t)b * D_DIM) + oct;
    const float4* z4 = reinterpret_cast<const float4*>(g_znorm + (size_t)row * D_DIM) + oct;
    float4* oq = reinterpret_cast<float4*>(zq_out + (size_t)row * D_DIM) + oct;

    float4 q = *e4;
    float4 zn = *z4;
    float d0 = q.x - zn.x, d1 = q.y - zn.y, d2 = q.z - zn.z, d3 = q.w - zn.w;
    float lsum = d0*d0 + d1*d1 + d2*d2 + d3*d3;
    *oq = q;

    red[threadIdx.x] = lsum;
    __syncthreads();
#pragma unroll
    for (int s = 128; s > 0; s >>= 1) {
        if (threadIdx.x < s) red[threadIdx.x] += red[threadIdx.x + s];
        __syncthreads();
    }
    if (threadIdx.x == 0) {
        long long qq = __double2ll_rn((double)red[0] * LOSS_SCALE);
        atomicAdd(&g_loss_acc, (unsigned long long)qq);
        __threadfence();
        unsigned int done = atomicAdd(&g_done, 1u);
        if (done == gridDim.x - 1) {
            double total = (double)(long long)g_loss_acc / LOSS_SCALE;
            loss_out[0] = (float)(1.25 * total / (double)(N_ROWS * D_DIM));
        }
    }
}

// ---------------- launch ----------------
extern "C" void kernel_launch(void* const* d_in, const int* in_sizes, int n_in,
                              void* d_out, int out_size) {
    const float* z   = (const float*)d_in[0];   // [32,1024,32]
    const float* emb = (const float*)d_in[1];   // [8192,32]
    float* out = (float*)d_out;

    float* zq_out   = out;                               // 1048576 floats
    float* loss_out = out + (size_t)N_ROWS * D_DIM;      // 1 float
    float* idx_out  = loss_out + 1;                      // 32768 floats

    cudaFuncSetAttribute(vq_approx, cudaFuncAttributeMaxDynamicSharedMemorySize, SMEM_APPROX);

    vq_prep<<<320, 256>>>(z, emb);
    vq_approx<<<GRID_APPROX, NTHR, SMEM_APPROX>>>(idx_out);
    vq_merge_flag<<<128, 256>>>(idx_out);
    vq_fix<<<1024, NTHR>>>();
    vq_out<<<1024, 256>>>(zq_out, idx_out, loss_out);
}